// round 2
// baseline (speedup 1.0000x reference)
#include <cuda_runtime.h>
#include <mma.h>
using namespace nvcuda;

// MultiHeadAttention: x[4,2048,1024], 16 heads, d=64, softmax scale 1/sqrt(1024)
// Pipeline: 3x TF32-wmma GEMM (QKV, head-split scatter) -> fused flash attention
// (TF32 wmma for QK^T and P*V, online softmax) -> TF32-wmma GEMM (output proj).

#define BB   4
#define NN   2048
#define EE   1024
#define HH   16
#define DD   64
#define MM   (BB*NN)   // 8192

// scratch (static device globals: allocation-free)
__device__ float g_Q[(size_t)MM*EE];   // [b,h,n,d]
__device__ float g_K[(size_t)MM*EE];   // [b,h,n,d]
__device__ float g_V[(size_t)MM*EE];   // [b,h,n,d]
__device__ float g_A[(size_t)MM*EE];   // attention out, [b,n,e] (heads merged)

// ---------------------------------------------------------------------------
// Generic TF32 GEMM: C = A[M,1024] @ W[1024,1024] + bias
// headSplit=1: scatter output to [b,h,n,d]; else row-major [M,1024].
// Block: 256 thr, tile 64(M) x 64(N), Kc = 32.
// ---------------------------------------------------------------------------
__global__ __launch_bounds__(256) void gemm_tf32(
    const float* __restrict__ A, const float* __restrict__ W,
    const float* __restrict__ bias, float* __restrict__ C, int headSplit)
{
    __shared__ float sh[64*32 + 32*64];   // As[64][32] | Bs[32][64]; reused as Cs[64][64]
    float* As = sh;
    float* Bs = sh + 64*32;

    const int m0 = blockIdx.y * 64;
    const int n0 = blockIdx.x * 64;
    const int tid = threadIdx.x;
    const int warp = tid >> 5;
    const int wr = warp & 3;       // 4 warp-rows of 16
    const int wc = warp >> 2;      // 2 warp-cols of 32

    wmma::fragment<wmma::accumulator,16,16,8,float> c0, c1;
    wmma::fill_fragment(c0, 0.0f);
    wmma::fill_fragment(c1, 0.0f);

    for (int kc = 0; kc < EE; kc += 32) {
        // A tile 64x32: 512 float4 loads
        #pragma unroll
        for (int i = 0; i < 2; i++) {
            int idx = tid + i*256;
            int r = idx >> 3, c4 = idx & 7;
            float4 v = *(const float4*)(A + (size_t)(m0 + r)*EE + kc + c4*4);
            float* d = As + r*32 + c4*4;
            d[0] = wmma::__float_to_tf32(v.x);
            d[1] = wmma::__float_to_tf32(v.y);
            d[2] = wmma::__float_to_tf32(v.z);
            d[3] = wmma::__float_to_tf32(v.w);
        }
        // W tile 32x64: 512 float4 loads
        #pragma unroll
        for (int i = 0; i < 2; i++) {
            int idx = tid + i*256;
            int r = idx >> 4, c4 = idx & 15;
            float4 v = *(const float4*)(W + (size_t)(kc + r)*EE + n0 + c4*4);
            float* d = Bs + r*64 + c4*4;
            d[0] = wmma::__float_to_tf32(v.x);
            d[1] = wmma::__float_to_tf32(v.y);
            d[2] = wmma::__float_to_tf32(v.z);
            d[3] = wmma::__float_to_tf32(v.w);
        }
        __syncthreads();
        #pragma unroll
        for (int kk = 0; kk < 4; kk++) {
            wmma::fragment<wmma::matrix_a,16,16,8,wmma::precision::tf32,wmma::row_major> a;
            wmma::load_matrix_sync(a, As + wr*16*32 + kk*8, 32);
            wmma::fragment<wmma::matrix_b,16,16,8,wmma::precision::tf32,wmma::row_major> b;
            wmma::load_matrix_sync(b, Bs + kk*8*64 + wc*32, 64);
            wmma::mma_sync(c0, a, b, c0);
            wmma::load_matrix_sync(b, Bs + kk*8*64 + wc*32 + 16, 64);
            wmma::mma_sync(c1, a, b, c1);
        }
        __syncthreads();
    }

    // epilogue via shared (reuse sh)
    float* Cs = sh;   // 64x64 = 4096 floats = exactly sh size
    wmma::store_matrix_sync(Cs + wr*16*64 + wc*32,      c0, 64, wmma::mem_row_major);
    wmma::store_matrix_sync(Cs + wr*16*64 + wc*32 + 16, c1, 64, wmma::mem_row_major);
    __syncthreads();

    for (int idx = tid; idx < 4096; idx += 256) {
        int rr = idx >> 6, cc = idx & 63;
        int m = m0 + rr, col = n0 + cc;
        float val = Cs[idx] + bias[col];
        if (headSplit) {
            int b  = m >> 11;        // m / 2048
            int nn = m & 2047;
            int h  = col >> 6;
            int dd = col & 63;
            C[((size_t)((b*HH + h)*NN + nn))*DD + dd] = val;
        } else {
            C[(size_t)m*EE + col] = val;
        }
    }
}

// ---------------------------------------------------------------------------
// Fused flash attention, one block per (b*h, q-tile of 64).
// S = (Q*scale) K^T via wmma; online softmax (fp32, shared); O += P V via wmma.
// Output written directly in merged-head layout [b, n, h*64+d].
// Dynamic smem: Qs(4096) KVs(4096) Ss(4096) Os(4096) m(64) l(64) = 66048 B.
// ---------------------------------------------------------------------------
__global__ __launch_bounds__(256) void attn_kernel(
    const float* __restrict__ Q, const float* __restrict__ K,
    const float* __restrict__ V, float* __restrict__ Aout)
{
    extern __shared__ float sh[];
    float* Qs   = sh;
    float* KVs  = sh + 4096;
    float* Ss   = sh + 8192;
    float* Os   = sh + 12288;
    float* mrow = sh + 16384;
    float* lrow = sh + 16448;

    const int q0  = blockIdx.x * 64;
    const int bh  = blockIdx.y;
    const int tid = threadIdx.x;
    const int warp = tid >> 5;
    const int wr = warp & 3;
    const int wc = warp >> 2;

    const float scale = 0.03125f;   // 1/sqrt(1024)
    const float* Qg = Q + (size_t)bh * NN * DD + (size_t)q0 * DD;
    const float* Kg = K + (size_t)bh * NN * DD;
    const float* Vg = V + (size_t)bh * NN * DD;

    // load Q tile (scaled, tf32)
    for (int i = tid; i < 1024; i += 256) {
        float4 v = ((const float4*)Qg)[i];
        float* d = Qs + i*4;
        d[0] = wmma::__float_to_tf32(v.x * scale);
        d[1] = wmma::__float_to_tf32(v.y * scale);
        d[2] = wmma::__float_to_tf32(v.z * scale);
        d[3] = wmma::__float_to_tf32(v.w * scale);
    }
    if (tid < 64) { mrow[tid] = -1e30f; lrow[tid] = 0.0f; }
    for (int i = tid; i < 4096; i += 256) Os[i] = 0.0f;

    const int row  = tid >> 2;   // 0..63
    const int part = tid & 3;    // 4 threads per row, 16 cols each

    for (int j = 0; j < NN/64; j++) {
        __syncthreads();   // prev iter's PV done with KVs/Os

        // load K tile (64 keys x 64 d), tf32
        const float* Kt = Kg + (size_t)j*64*DD;
        for (int i = tid; i < 1024; i += 256) {
            float4 v = ((const float4*)Kt)[i];
            float* d = KVs + i*4;
            d[0] = wmma::__float_to_tf32(v.x);
            d[1] = wmma::__float_to_tf32(v.y);
            d[2] = wmma::__float_to_tf32(v.z);
            d[3] = wmma::__float_to_tf32(v.w);
        }
        __syncthreads();

        // S = Qs @ KVs^T   (K^T is col_major view of K[key][d], ld=64)
        {
            wmma::fragment<wmma::accumulator,16,16,8,float> s0, s1;
            wmma::fill_fragment(s0, 0.0f);
            wmma::fill_fragment(s1, 0.0f);
            #pragma unroll
            for (int kk = 0; kk < 8; kk++) {
                wmma::fragment<wmma::matrix_a,16,16,8,wmma::precision::tf32,wmma::row_major> a;
                wmma::load_matrix_sync(a, Qs + wr*16*64 + kk*8, 64);
                wmma::fragment<wmma::matrix_b,16,16,8,wmma::precision::tf32,wmma::col_major> b;
                wmma::load_matrix_sync(b, KVs + (wc*32)*64 + kk*8, 64);
                wmma::mma_sync(s0, a, b, s0);
                wmma::load_matrix_sync(b, KVs + (wc*32 + 16)*64 + kk*8, 64);
                wmma::mma_sync(s1, a, b, s1);
            }
            wmma::store_matrix_sync(Ss + wr*16*64 + wc*32,      s0, 64, wmma::mem_row_major);
            wmma::store_matrix_sync(Ss + wr*16*64 + wc*32 + 16, s1, 64, wmma::mem_row_major);
        }
        __syncthreads();

        // online softmax update (each quad owns one row)
        {
            float sv[16];
            float mx = -1e30f;
            float* srow = Ss + row*64 + part*16;
            #pragma unroll
            for (int i = 0; i < 16; i++) { sv[i] = srow[i]; mx = fmaxf(mx, sv[i]); }
            mx = fmaxf(mx, __shfl_xor_sync(0xffffffffu, mx, 1));
            mx = fmaxf(mx, __shfl_xor_sync(0xffffffffu, mx, 2));
            float m_old = mrow[row];
            float m_new = fmaxf(m_old, mx);
            float alpha = __expf(m_old - m_new);
            float sum = 0.0f;
            #pragma unroll
            for (int i = 0; i < 16; i++) {
                float p = __expf(sv[i] - m_new);
                sum += p;
                srow[i] = wmma::__float_to_tf32(p);
            }
            sum += __shfl_xor_sync(0xffffffffu, sum, 1);
            sum += __shfl_xor_sync(0xffffffffu, sum, 2);
            if (part == 0) { mrow[row] = m_new; lrow[row] = lrow[row]*alpha + sum; }
            float* orow = Os + row*64 + part*16;
            #pragma unroll
            for (int i = 0; i < 16; i++) orow[i] *= alpha;
        }

        // load V tile into KVs (QK mma reads finished before last sync)
        const float* Vt = Vg + (size_t)j*64*DD;
        for (int i = tid; i < 1024; i += 256) {
            float4 v = ((const float4*)Vt)[i];
            float* d = KVs + i*4;
            d[0] = wmma::__float_to_tf32(v.x);
            d[1] = wmma::__float_to_tf32(v.y);
            d[2] = wmma::__float_to_tf32(v.z);
            d[3] = wmma::__float_to_tf32(v.w);
        }
        __syncthreads();

        // O += P @ V
        {
            wmma::fragment<wmma::accumulator,16,16,8,float> o0, o1;
            wmma::load_matrix_sync(o0, Os + wr*16*64 + wc*32,      64, wmma::mem_row_major);
            wmma::load_matrix_sync(o1, Os + wr*16*64 + wc*32 + 16, 64, wmma::mem_row_major);
            #pragma unroll
            for (int kk = 0; kk < 8; kk++) {
                wmma::fragment<wmma::matrix_a,16,16,8,wmma::precision::tf32,wmma::row_major> a;
                wmma::load_matrix_sync(a, Ss + wr*16*64 + kk*8, 64);
                wmma::fragment<wmma::matrix_b,16,16,8,wmma::precision::tf32,wmma::row_major> b;
                wmma::load_matrix_sync(b, KVs + kk*8*64 + wc*32, 64);
                wmma::mma_sync(o0, a, b, o0);
                wmma::load_matrix_sync(b, KVs + kk*8*64 + wc*32 + 16, 64);
                wmma::mma_sync(o1, a, b, o1);
            }
            wmma::store_matrix_sync(Os + wr*16*64 + wc*32,      o0, 64, wmma::mem_row_major);
            wmma::store_matrix_sync(Os + wr*16*64 + wc*32 + 16, o1, 64, wmma::mem_row_major);
        }
    }
    __syncthreads();

    // write out: Aout[b][q0+row][h*64 + d] = Os / l
    {
        int b = bh >> 4, h = bh & 15;
        float inv = 1.0f / lrow[row];
        float* orow = Os + row*64 + part*16;
        float* dst = Aout + ((size_t)(b*NN + q0 + row))*EE + h*64 + part*16;
        #pragma unroll
        for (int i = 0; i < 16; i++) dst[i] = orow[i] * inv;
    }
}

// ---------------------------------------------------------------------------
extern "C" void kernel_launch(void* const* d_in, const int* in_sizes, int n_in,
                              void* d_out, int out_size)
{
    const float* x  = (const float*)d_in[0];
    const float* Wq = (const float*)d_in[1];
    const float* bq = (const float*)d_in[2];
    const float* Wk = (const float*)d_in[3];
    const float* bk = (const float*)d_in[4];
    const float* Wv = (const float*)d_in[5];
    const float* bv = (const float*)d_in[6];
    const float* Wo = (const float*)d_in[7];
    const float* bo = (const float*)d_in[8];

    float *Qp, *Kp, *Vp, *Ap;
    cudaGetSymbolAddress((void**)&Qp, g_Q);
    cudaGetSymbolAddress((void**)&Kp, g_K);
    cudaGetSymbolAddress((void**)&Vp, g_V);
    cudaGetSymbolAddress((void**)&Ap, g_A);

    dim3 ggrid(EE/64, MM/64);   // (16, 128)
    gemm_tf32<<<ggrid, 256>>>(x, Wq, bq, Qp, 1);
    gemm_tf32<<<ggrid, 256>>>(x, Wk, bk, Kp, 1);
    gemm_tf32<<<ggrid, 256>>>(x, Wv, bv, Vp, 1);

    const int smem = 16512 * (int)sizeof(float);   // 66048 B
    cudaFuncSetAttribute(attn_kernel, cudaFuncAttributeMaxDynamicSharedMemorySize, smem);
    attn_kernel<<<dim3(NN/64, BB*HH), 256, smem>>>(Qp, Kp, Vp, Ap);

    gemm_tf32<<<ggrid, 256>>>(Ap, Wo, bo, (float*)d_out, 0);
}

// round 5
// speedup vs baseline: 5.3407x; 5.3407x over previous
#include <cuda_runtime.h>
#include <cstdint>

// MultiHeadAttention x[4,2048,1024], 16 heads, d=64, scale 1/sqrt(1024)
// PTX mma.m16n8k8.tf32 everywhere, cp.async double-buffered tiles,
// register-resident Q fragments + O accumulators in flash attention.

#define BB 4
#define NN 2048
#define EE 1024
#define HH 16
#define DD 64
#define MM (BB*NN)      // 8192

__device__ float g_X [(size_t)MM*EE];     // tf32-converted x
__device__ float g_Wc[(size_t)4*EE*EE];   // tf32-converted Wq,Wk,Wv,Wo
__device__ float g_Q [(size_t)MM*EE];     // [b,h,n,d] (tf32 values)
__device__ float g_K [(size_t)MM*EE];
__device__ float g_V [(size_t)MM*EE];
__device__ float g_A [(size_t)MM*EE];     // attn out [b,n,e] (tf32 values)

// ---------------------------------------------------------------- helpers
__device__ __forceinline__ float to_tf32(float x) {
    float r; asm("cvt.rna.tf32.f32 %0, %1;" : "=f"(r) : "f"(x)); return r;
}
__device__ __forceinline__ void mma8(float c[4], const uint32_t a[4], const uint32_t b[2]) {
    asm volatile("mma.sync.aligned.m16n8k8.row.col.f32.tf32.tf32.f32 "
                 "{%0,%1,%2,%3}, {%4,%5,%6,%7}, {%8,%9}, {%0,%1,%2,%3};\n"
                 : "+f"(c[0]), "+f"(c[1]), "+f"(c[2]), "+f"(c[3])
                 : "r"(a[0]), "r"(a[1]), "r"(a[2]), "r"(a[3]), "r"(b[0]), "r"(b[1]));
}
__device__ __forceinline__ void cpa16(float* smem, const float* g) {
    uint32_t s = (uint32_t)__cvta_generic_to_shared(smem);
    asm volatile("cp.async.cg.shared.global [%0], [%1], 16;\n" :: "r"(s), "l"(g));
}
#define CP_COMMIT() asm volatile("cp.async.commit_group;\n")
#define CP_WAIT1()  asm volatile("cp.async.wait_group 1;\n")
#define CP_WAIT0()  asm volatile("cp.async.wait_group 0;\n")
__device__ __forceinline__ uint32_t fb(float x) { return __float_as_uint(x); }

// ---------------------------------------------------------------- tf32 convert
__global__ void conv_tf32(const float* __restrict__ src, float* __restrict__ dst, int n4) {
    int i = blockIdx.x * blockDim.x + threadIdx.x;
    if (i < n4) {
        float4 v = ((const float4*)src)[i];
        v.x = to_tf32(v.x); v.y = to_tf32(v.y);
        v.z = to_tf32(v.z); v.w = to_tf32(v.w);
        ((float4*)dst)[i] = v;
    }
}

// ---------------------------------------------------------------- GEMM
// C[M,1024] = A[M,1024] @ W[1024,1024] + bias. A, W pre-converted tf32.
// Block 256 thr, tile 128x128, Kc=32, double-buffered cp.async.
// mode 1: tf32-convert output + scatter [b,h,n,d]; mode 0: raw row-major.
#define GA_LD 40
#define GB_LD 136
#define GEMM_SMEM ((2*128*GA_LD + 2*32*GB_LD) * 4)

__global__ __launch_bounds__(256) void gemm_tf32(
    const float* __restrict__ A, const float* __restrict__ W,
    const float* __restrict__ bias, float* __restrict__ C, int mode)
{
    extern __shared__ float sh[];
    float* As = sh;                      // 2 x 128 x GA_LD
    float* Bs = sh + 2*128*GA_LD;        // 2 x 32 x GB_LD

    const int m0 = blockIdx.y * 128, n0 = blockIdx.x * 128;
    const int tid = threadIdx.x, lane = tid & 31, warp = tid >> 5;
    const int wm = warp & 1, wn = warp >> 1;       // 2 x 4 warp grid (64 x 32 each)
    const int g = lane >> 2, t = lane & 3;

    float acc[4][4][4];
    #pragma unroll
    for (int a = 0; a < 4; a++)
        #pragma unroll
        for (int b = 0; b < 4; b++)
            #pragma unroll
            for (int c = 0; c < 4; c++) acc[a][b][c] = 0.0f;

    auto loadTiles = [&](int kc, int buf) {
        float* Ad = As + buf * 128 * GA_LD;
        #pragma unroll
        for (int i = 0; i < 4; i++) {
            int idx = tid + i * 256; int r = idx >> 3, c = idx & 7;
            cpa16(Ad + r * GA_LD + c * 4, A + (size_t)(m0 + r) * EE + kc + c * 4);
        }
        float* Bd = Bs + buf * 32 * GB_LD;
        #pragma unroll
        for (int i = 0; i < 4; i++) {
            int idx = tid + i * 256; int r = idx >> 5, c = idx & 31;
            cpa16(Bd + r * GB_LD + c * 4, W + (size_t)(kc + r) * EE + n0 + c * 4);
        }
        CP_COMMIT();
    };

    loadTiles(0, 0);
    for (int j = 0; j < 32; j++) {
        if (j + 1 < 32) { loadTiles((j + 1) * 32, (j + 1) & 1); CP_WAIT1(); }
        else            { CP_WAIT0(); }
        __syncthreads();

        const float* Ab = As + (j & 1) * 128 * GA_LD + wm * 64 * GA_LD;
        const float* Bb = Bs + (j & 1) * 32 * GB_LD + wn * 32;
        #pragma unroll
        for (int ks = 0; ks < 4; ks++) {
            uint32_t af[4][4];
            #pragma unroll
            for (int mt = 0; mt < 4; mt++) {
                const float* p = Ab + (mt * 16 + g) * GA_LD + ks * 8 + t;
                af[mt][0] = fb(p[0]);
                af[mt][1] = fb(p[8 * GA_LD]);
                af[mt][2] = fb(p[4]);
                af[mt][3] = fb(p[8 * GA_LD + 4]);
            }
            #pragma unroll
            for (int nt = 0; nt < 4; nt++) {
                const float* q = Bb + (ks * 8 + t) * GB_LD + nt * 8 + g;
                uint32_t bf[2] = { fb(q[0]), fb(q[4 * GB_LD]) };
                #pragma unroll
                for (int mt = 0; mt < 4; mt++) mma8(acc[mt][nt], af[mt], bf);
            }
        }
        __syncthreads();
    }

    // epilogue
    #pragma unroll
    for (int nt = 0; nt < 4; nt++) {
        int col = n0 + wn * 32 + nt * 8 + 2 * t;
        float b0 = bias[col], b1 = bias[col + 1];
        #pragma unroll
        for (int mt = 0; mt < 4; mt++) {
            int r0 = m0 + wm * 64 + mt * 16 + g;
            float v00 = acc[mt][nt][0] + b0, v01 = acc[mt][nt][1] + b1;
            float v10 = acc[mt][nt][2] + b0, v11 = acc[mt][nt][3] + b1;
            if (mode == 1) {
                v00 = to_tf32(v00); v01 = to_tf32(v01);
                v10 = to_tf32(v10); v11 = to_tf32(v11);
                int b  = r0 >> 11;
                int h  = col >> 6, dd = col & 63;
                int nn0 = r0 & 2047;
                size_t base = ((size_t)((b * HH + h) * NN)) * DD + dd;
                *(float2*)(C + base + (size_t)nn0 * DD)       = make_float2(v00, v01);
                *(float2*)(C + base + (size_t)(nn0 + 8) * DD) = make_float2(v10, v11);
            } else {
                *(float2*)(C + (size_t)r0 * EE + col)       = make_float2(v00, v01);
                *(float2*)(C + (size_t)(r0 + 8) * EE + col) = make_float2(v10, v11);
            }
        }
    }
}

// ---------------------------------------------------------------- attention
// Block: 128 thr (4 warps), 64 q rows; warp owns 16 rows.
// Q fragments + O accumulators register-resident; K/V double-buffered cp.async.
// P tile is 16x64 per warp -> PS_LD must be >= 64 (72 = conflict-free pad).
#define KS_LD 68
#define VS_LD 72
#define PS_LD 72
#define ATTN_SMEM ((2*64*KS_LD + 2*64*VS_LD + 4*16*PS_LD) * 4)   // 90112 B

__global__ __launch_bounds__(128) void attn_kernel(
    const float* __restrict__ Q, const float* __restrict__ K,
    const float* __restrict__ V, float* __restrict__ Aout)
{
    extern __shared__ float sh[];
    float* Ks = sh;                          // 2 x 64 x KS_LD
    float* Vs = sh + 2 * 64 * KS_LD;         // 2 x 64 x VS_LD
    float* Ps = Vs + 2 * 64 * VS_LD;         // 4 x 16 x PS_LD

    const int q0 = blockIdx.x * 64, bh = blockIdx.y;
    const int tid = threadIdx.x, lane = tid & 31, warp = tid >> 5;
    const int g = lane >> 2, t = lane & 3;

    const float* Qg = Q + (size_t)bh * NN * DD + (size_t)q0 * DD;
    const float* Kg = K + (size_t)bh * NN * DD;
    const float* Vg = V + (size_t)bh * NN * DD;

    // Q fragments in registers (scale 2^-5 exact, stays tf32)
    uint32_t qf[8][4];
    {
        const float* p = Qg + (warp * 16 + g) * DD + t;
        #pragma unroll
        for (int k = 0; k < 8; k++) {
            qf[k][0] = fb(p[k * 8]              * 0.03125f);
            qf[k][1] = fb(p[8 * DD + k * 8]     * 0.03125f);
            qf[k][2] = fb(p[k * 8 + 4]          * 0.03125f);
            qf[k][3] = fb(p[8 * DD + k * 8 + 4] * 0.03125f);
        }
    }

    float O[8][4];
    #pragma unroll
    for (int nt = 0; nt < 8; nt++)
        #pragma unroll
        for (int i = 0; i < 4; i++) O[nt][i] = 0.0f;
    float m0r = -1e30f, m1r = -1e30f, l0 = 0.0f, l1 = 0.0f;

    float* Pw = Ps + warp * 16 * PS_LD;

    auto loadKV = [&](int j, int buf) {
        const float* Kt = Kg + (size_t)j * 64 * DD;
        const float* Vt = Vg + (size_t)j * 64 * DD;
        float* Kd = Ks + buf * 64 * KS_LD;
        float* Vd = Vs + buf * 64 * VS_LD;
        #pragma unroll
        for (int i = 0; i < 8; i++) {
            int idx = tid + i * 128; int r = idx >> 4, c = idx & 15;
            cpa16(Kd + r * KS_LD + c * 4, Kt + r * DD + c * 4);
        }
        #pragma unroll
        for (int i = 0; i < 8; i++) {
            int idx = tid + i * 128; int r = idx >> 4, c = idx & 15;
            cpa16(Vd + r * VS_LD + c * 4, Vt + r * DD + c * 4);
        }
        CP_COMMIT();
    };

    loadKV(0, 0);
    for (int j = 0; j < NN / 64; j++) {
        if (j + 1 < NN / 64) { loadKV(j + 1, (j + 1) & 1); CP_WAIT1(); }
        else                 { CP_WAIT0(); }
        __syncthreads();

        const float* Kb = Ks + (j & 1) * 64 * KS_LD;
        const float* Vb = Vs + (j & 1) * 64 * VS_LD;

        // S = (Q*scale) K^T  (16 x 64 per warp)
        float S[8][4];
        #pragma unroll
        for (int nt = 0; nt < 8; nt++)
            #pragma unroll
            for (int i = 0; i < 4; i++) S[nt][i] = 0.0f;
        #pragma unroll
        for (int k = 0; k < 8; k++) {
            #pragma unroll
            for (int nt = 0; nt < 8; nt++) {
                const float* q = Kb + (nt * 8 + g) * KS_LD + k * 8 + t;
                uint32_t bf[2] = { fb(q[0]), fb(q[4]) };
                mma8(S[nt], qf[k], bf);
            }
        }

        // online softmax in accumulator layout (rows g, g+8; cols nt*8+2t,+1)
        float mx0 = -1e30f, mx1 = -1e30f;
        #pragma unroll
        for (int nt = 0; nt < 8; nt++) {
            mx0 = fmaxf(mx0, fmaxf(S[nt][0], S[nt][1]));
            mx1 = fmaxf(mx1, fmaxf(S[nt][2], S[nt][3]));
        }
        mx0 = fmaxf(mx0, __shfl_xor_sync(0xffffffffu, mx0, 1));
        mx0 = fmaxf(mx0, __shfl_xor_sync(0xffffffffu, mx0, 2));
        mx1 = fmaxf(mx1, __shfl_xor_sync(0xffffffffu, mx1, 1));
        mx1 = fmaxf(mx1, __shfl_xor_sync(0xffffffffu, mx1, 2));
        float mn0 = fmaxf(m0r, mx0), mn1 = fmaxf(m1r, mx1);
        float a0 = __expf(m0r - mn0), a1 = __expf(m1r - mn1);
        float s0 = 0.0f, s1 = 0.0f;
        #pragma unroll
        for (int nt = 0; nt < 8; nt++) {
            float p00 = __expf(S[nt][0] - mn0);
            float p01 = __expf(S[nt][1] - mn0);
            float p10 = __expf(S[nt][2] - mn1);
            float p11 = __expf(S[nt][3] - mn1);
            s0 += p00 + p01; s1 += p10 + p11;
            int c = nt * 8 + 2 * t;
            Pw[g * PS_LD + c]           = to_tf32(p00);
            Pw[g * PS_LD + c + 1]       = to_tf32(p01);
            Pw[(g + 8) * PS_LD + c]     = to_tf32(p10);
            Pw[(g + 8) * PS_LD + c + 1] = to_tf32(p11);
        }
        s0 += __shfl_xor_sync(0xffffffffu, s0, 1);
        s0 += __shfl_xor_sync(0xffffffffu, s0, 2);
        s1 += __shfl_xor_sync(0xffffffffu, s1, 1);
        s1 += __shfl_xor_sync(0xffffffffu, s1, 2);
        l0 = l0 * a0 + s0; l1 = l1 * a1 + s1;
        m0r = mn0; m1r = mn1;
        #pragma unroll
        for (int nt = 0; nt < 8; nt++) {
            O[nt][0] *= a0; O[nt][1] *= a0;
            O[nt][2] *= a1; O[nt][3] *= a1;
        }
        __syncwarp();

        // O += P @ V
        #pragma unroll
        for (int k = 0; k < 8; k++) {
            uint32_t pa[4];
            const float* pp = Pw + g * PS_LD + k * 8 + t;
            pa[0] = fb(pp[0]);
            pa[1] = fb(pp[8 * PS_LD]);
            pa[2] = fb(pp[4]);
            pa[3] = fb(pp[8 * PS_LD + 4]);
            #pragma unroll
            for (int nt = 0; nt < 8; nt++) {
                const float* q = Vb + (k * 8 + t) * VS_LD + nt * 8 + g;
                uint32_t bf[2] = { fb(q[0]), fb(q[4 * VS_LD]) };
                mma8(O[nt], pa, bf);
            }
        }
        __syncthreads();
    }

    // write out [b, n, h*64+d], tf32-converted (feeds O-proj GEMM)
    {
        int b = bh >> 4, h = bh & 15;
        float i0 = 1.0f / l0, i1 = 1.0f / l1;
        int r = q0 + warp * 16 + g;
        float* d0 = Aout + ((size_t)(b * NN + r)) * EE + h * 64;
        float* d1 = d0 + (size_t)8 * EE;
        #pragma unroll
        for (int nt = 0; nt < 8; nt++) {
            int c = nt * 8 + 2 * t;
            *(float2*)(d0 + c) = make_float2(to_tf32(O[nt][0] * i0), to_tf32(O[nt][1] * i0));
            *(float2*)(d1 + c) = make_float2(to_tf32(O[nt][2] * i1), to_tf32(O[nt][3] * i1));
        }
    }
}

// ---------------------------------------------------------------- launch
extern "C" void kernel_launch(void* const* d_in, const int* in_sizes, int n_in,
                              void* d_out, int out_size)
{
    const float* x  = (const float*)d_in[0];
    const float* Wq = (const float*)d_in[1];
    const float* bq = (const float*)d_in[2];
    const float* Wk = (const float*)d_in[3];
    const float* bk = (const float*)d_in[4];
    const float* Wv = (const float*)d_in[5];
    const float* bv = (const float*)d_in[6];
    const float* Wo = (const float*)d_in[7];
    const float* bo = (const float*)d_in[8];

    float *Xp, *Wcp, *Qp, *Kp, *Vp, *Ap;
    cudaGetSymbolAddress((void**)&Xp,  g_X);
    cudaGetSymbolAddress((void**)&Wcp, g_Wc);
    cudaGetSymbolAddress((void**)&Qp,  g_Q);
    cudaGetSymbolAddress((void**)&Kp,  g_K);
    cudaGetSymbolAddress((void**)&Vp,  g_V);
    cudaGetSymbolAddress((void**)&Ap,  g_A);

    cudaFuncSetAttribute(gemm_tf32, cudaFuncAttributeMaxDynamicSharedMemorySize, GEMM_SMEM);
    cudaFuncSetAttribute(attn_kernel, cudaFuncAttributeMaxDynamicSharedMemorySize, ATTN_SMEM);

    // tf32 pre-conversion
    {
        int n4x = MM * EE / 4;          // 2,097,152
        int n4w = EE * EE / 4;          // 262,144
        conv_tf32<<<(n4x + 255) / 256, 256>>>(x,  Xp, n4x);
        conv_tf32<<<(n4w + 255) / 256, 256>>>(Wq, Wcp + (size_t)0 * EE * EE, n4w);
        conv_tf32<<<(n4w + 255) / 256, 256>>>(Wk, Wcp + (size_t)1 * EE * EE, n4w);
        conv_tf32<<<(n4w + 255) / 256, 256>>>(Wv, Wcp + (size_t)2 * EE * EE, n4w);
        conv_tf32<<<(n4w + 255) / 256, 256>>>(Wo, Wcp + (size_t)3 * EE * EE, n4w);
    }

    dim3 ggrid(EE / 128, MM / 128);     // (8, 64)
    gemm_tf32<<<ggrid, 256, GEMM_SMEM>>>(Xp, Wcp + (size_t)0 * EE * EE, bq, Qp, 1);
    gemm_tf32<<<ggrid, 256, GEMM_SMEM>>>(Xp, Wcp + (size_t)1 * EE * EE, bk, Kp, 1);
    gemm_tf32<<<ggrid, 256, GEMM_SMEM>>>(Xp, Wcp + (size_t)2 * EE * EE, bv, Vp, 1);

    attn_kernel<<<dim3(NN / 64, BB * HH), 128, ATTN_SMEM>>>(Qp, Kp, Vp, Ap);

    gemm_tf32<<<ggrid, 256, GEMM_SMEM>>>(Ap, Wcp + (size_t)3 * EE * EE, bo, (float*)d_out, 0);
}

// round 8
// speedup vs baseline: 5.5741x; 1.0437x over previous
#include <cuda_runtime.h>
#include <cstdint>

// MultiHeadAttention x[4,2048,1024], 16 heads, d=64, scale 1/sqrt(1024)
// mma.m16n8k8.tf32; 64x64 warp tiles; pair-permuted A layout (cols within each
// 8-group stored 0,4,1,5,2,6,3,7) so A fragments load as float2; fused QKV GEMM.

#define BB 4
#define NN 2048
#define EE 1024
#define HH 16
#define DD 64
#define MM (BB*NN)      // 8192

__device__ float g_X  [(size_t)MM*EE];      // tf32 x, A-permuted
__device__ float g_Wc [(size_t)4*EE*EE];    // tf32 Wq,Wk,Wv,Wo (standard layout)
__device__ float g_Bc [3*EE];               // concat bq,bk,bv
__device__ float g_QKV[(size_t)3*MM*EE];    // Q|K|V in [b,h,n,d]
__device__ float g_A  [(size_t)MM*EE];      // attn out [b,n,e], tf32, A-permuted

// ---------------------------------------------------------------- helpers
__device__ __forceinline__ float to_tf32(float x) {
    float r; asm("cvt.rna.tf32.f32 %0, %1;" : "=f"(r) : "f"(x)); return r;
}
__device__ __forceinline__ void mma8(float c[4], const uint32_t a[4], const uint32_t b[2]) {
    asm volatile("mma.sync.aligned.m16n8k8.row.col.f32.tf32.tf32.f32 "
                 "{%0,%1,%2,%3}, {%4,%5,%6,%7}, {%8,%9}, {%0,%1,%2,%3};\n"
                 : "+f"(c[0]), "+f"(c[1]), "+f"(c[2]), "+f"(c[3])
                 : "r"(a[0]), "r"(a[1]), "r"(a[2]), "r"(a[3]), "r"(b[0]), "r"(b[1]));
}
__device__ __forceinline__ void cpa16(float* smem, const float* g) {
    uint32_t s = (uint32_t)__cvta_generic_to_shared(smem);
    asm volatile("cp.async.cg.shared.global [%0], [%1], 16;\n" :: "r"(s), "l"(g));
}
#define CP_COMMIT() asm volatile("cp.async.commit_group;\n")
#define CP_WAIT1()  asm volatile("cp.async.wait_group 1;\n")
#define CP_WAIT0()  asm volatile("cp.async.wait_group 0;\n")
__device__ __forceinline__ uint32_t fb(float x) { return __float_as_uint(x); }

// ---------------------------------------------------------------- convs
// straight tf32 copy (weights / B-side)
__global__ void conv_tf32(const float* __restrict__ src, float* __restrict__ dst, int n4) {
    int i = blockIdx.x * blockDim.x + threadIdx.x;
    if (i < n4) {
        float4 v = ((const float4*)src)[i];
        v.x = to_tf32(v.x); v.y = to_tf32(v.y);
        v.z = to_tf32(v.z); v.w = to_tf32(v.w);
        ((float4*)dst)[i] = v;
    }
}
// tf32 + A-permute: logical col j in 8-group -> physical (j&3)*2 + (j>>2)
__global__ void conv_perm(const float* __restrict__ src, float* __restrict__ dst, int n4) {
    int i = blockIdx.x * blockDim.x + threadIdx.x;
    if (i < n4) {
        float4 v = ((const float4*)src)[i];
        int c4 = i & 255;                  // EE/4 float4s per row
        int row = i >> 8;
        int g8 = (c4 >> 1) * 8;            // 8-col group start
        int odd = c4 & 1;                  // logical cols 4*odd .. 4*odd+3
        float* d = dst + (size_t)row * EE + g8 + odd;
        d[0] = to_tf32(v.x); d[2] = to_tf32(v.y);
        d[4] = to_tf32(v.z); d[6] = to_tf32(v.w);
    }
}
__global__ void concat_bias(const float* a, const float* b, const float* c, float* dst) {
    int i = threadIdx.x + blockIdx.x * blockDim.x;   // 1024 threads
    dst[i] = a[i]; dst[i + EE] = b[i]; dst[i + 2*EE] = c[i];
}

// ---------------------------------------------------------------- GEMM
// C = A[M,1024](permuted tf32) @ W + bias.  Block 128 thr (4 warps), tile
// 128x128, warp tile 64x64, Kc=32, double-buffered cp.async.
// mode 1: fused QKV (N=3072): W/bias concatenated, scatter to [b,h,n,d].
// mode 0: O-proj: standard row-major out.
#define GA_LD 40
#define GB_LD 136
#define GEMM_SMEM ((2*128*GA_LD + 2*32*GB_LD) * 4)   // 75776 B

__global__ __launch_bounds__(128) void gemm_tf32(
    const float* __restrict__ A, const float* __restrict__ Wbase,
    const float* __restrict__ bias, float* __restrict__ C, int mode)
{
    extern __shared__ float sh[];
    float* As = sh;                      // 2 x 128 x GA_LD
    float* Bs = sh + 2*128*GA_LD;        // 2 x 32 x GB_LD

    const int m0 = blockIdx.y * 128, n0 = blockIdx.x * 128;
    const int tid = threadIdx.x, lane = tid & 31, warp = tid >> 5;
    const int wm = warp & 1, wn = warp >> 1;       // 2x2 warps of 64x64
    const int g = lane >> 2, t = lane & 3;

    // weight slab for this block's n-range (n0 within one 1024-col weight)
    const float* W = Wbase + (size_t)(n0 >> 10) * EE * EE;
    const int ncol0 = n0 & 1023;

    float acc[4][8][4];
    #pragma unroll
    for (int a = 0; a < 4; a++)
        #pragma unroll
        for (int b = 0; b < 8; b++)
            #pragma unroll
            for (int c = 0; c < 4; c++) acc[a][b][c] = 0.0f;

    auto loadTiles = [&](int kc, int buf) {
        float* Ad = As + buf * 128 * GA_LD;
        #pragma unroll
        for (int i = 0; i < 8; i++) {
            int idx = tid + i * 128; int r = idx >> 3, c = idx & 7;
            cpa16(Ad + r * GA_LD + c * 4, A + (size_t)(m0 + r) * EE + kc + c * 4);
        }
        float* Bd = Bs + buf * 32 * GB_LD;
        #pragma unroll
        for (int i = 0; i < 8; i++) {
            int idx = tid + i * 128; int r = idx >> 5, c = idx & 31;
            cpa16(Bd + r * GB_LD + c * 4, W + (size_t)(kc + r) * EE + ncol0 + c * 4);
        }
        CP_COMMIT();
    };

    loadTiles(0, 0);
    for (int j = 0; j < 32; j++) {
        if (j + 1 < 32) { loadTiles((j + 1) * 32, (j + 1) & 1); CP_WAIT1(); }
        else            { CP_WAIT0(); }
        __syncthreads();

        const float* Ab = As + (j & 1) * 128 * GA_LD + wm * 64 * GA_LD;
        const float* Bb = Bs + (j & 1) * 32 * GB_LD + wn * 64;
        #pragma unroll
        for (int ks = 0; ks < 4; ks++) {
            // A fragments: permuted layout -> float2 per row
            uint32_t af[4][4];
            #pragma unroll
            for (int mt = 0; mt < 4; mt++) {
                const float* p = Ab + (mt * 16 + g) * GA_LD + ks * 8 + 2 * t;
                float2 v0 = *(const float2*)p;                 // rows g: (t, t+4)
                float2 v1 = *(const float2*)(p + 8 * GA_LD);   // rows g+8
                af[mt][0] = fb(v0.x); af[mt][2] = fb(v0.y);
                af[mt][1] = fb(v1.x); af[mt][3] = fb(v1.y);
            }
            #pragma unroll
            for (int nt = 0; nt < 8; nt++) {
                const float* q = Bb + (ks * 8 + t) * GB_LD + nt * 8 + g;
                uint32_t bf[2] = { fb(q[0]), fb(q[4 * GB_LD]) };
                #pragma unroll
                for (int mt = 0; mt < 4; mt++) mma8(acc[mt][nt], af[mt], bf);
            }
        }
        __syncthreads();
    }

    // epilogue
    #pragma unroll
    for (int nt = 0; nt < 8; nt++) {
        int col = n0 + wn * 64 + nt * 8 + 2 * t;        // global fused col
        float b0 = bias[col], b1 = bias[col + 1];
        #pragma unroll
        for (int mt = 0; mt < 4; mt++) {
            int r0 = m0 + wm * 64 + mt * 16 + g;
            float v00 = acc[mt][nt][0] + b0, v01 = acc[mt][nt][1] + b1;
            float v10 = acc[mt][nt][2] + b0, v11 = acc[mt][nt][3] + b1;
            if (mode == 1) {
                v00 = to_tf32(v00); v01 = to_tf32(v01);
                v10 = to_tf32(v10); v11 = to_tf32(v11);
                int widx = col >> 10, col1 = col & 1023;
                int b  = r0 >> 11;
                int h  = col1 >> 6, dd = col1 & 63;
                int nn0 = r0 & 2047;
                float* Cq = C + (size_t)widx * MM * EE;
                size_t base = ((size_t)((b * HH + h) * NN)) * DD + dd;
                *(float2*)(Cq + base + (size_t)nn0 * DD)       = make_float2(v00, v01);
                *(float2*)(Cq + base + (size_t)(nn0 + 8) * DD) = make_float2(v10, v11);
            } else {
                *(float2*)(C + (size_t)r0 * EE + col)       = make_float2(v00, v01);
                *(float2*)(C + (size_t)(r0 + 8) * EE + col) = make_float2(v10, v11);
            }
        }
    }
}

// ---------------------------------------------------------------- attention
// Block: 128 thr (4 warps), 64 q rows; warp owns 16 rows.
// Q fragments + O accumulators register-resident; K/V double-buffered cp.async.
#define KS_LD 68
#define VS_LD 72
#define PS_LD 72
#define ATTN_SMEM ((2*64*KS_LD + 2*64*VS_LD + 4*16*PS_LD) * 4)   // 90112 B

__global__ __launch_bounds__(128) void attn_kernel(
    const float* __restrict__ Q, const float* __restrict__ K,
    const float* __restrict__ V, float* __restrict__ Aout)
{
    extern __shared__ float sh[];
    float* Ks = sh;
    float* Vs = sh + 2 * 64 * KS_LD;
    float* Ps = Vs + 2 * 64 * VS_LD;

    const int q0 = blockIdx.x * 64, bh = blockIdx.y;
    const int tid = threadIdx.x, lane = tid & 31, warp = tid >> 5;
    const int g = lane >> 2, t = lane & 3;

    const float* Qg = Q + (size_t)bh * NN * DD + (size_t)q0 * DD;
    const float* Kg = K + (size_t)bh * NN * DD;
    const float* Vg = V + (size_t)bh * NN * DD;

    uint32_t qf[8][4];
    {
        const float* p = Qg + (warp * 16 + g) * DD + t;
        #pragma unroll
        for (int k = 0; k < 8; k++) {
            qf[k][0] = fb(p[k * 8]              * 0.03125f);
            qf[k][1] = fb(p[8 * DD + k * 8]     * 0.03125f);
            qf[k][2] = fb(p[k * 8 + 4]          * 0.03125f);
            qf[k][3] = fb(p[8 * DD + k * 8 + 4] * 0.03125f);
        }
    }

    float O[8][4];
    #pragma unroll
    for (int nt = 0; nt < 8; nt++)
        #pragma unroll
        for (int i = 0; i < 4; i++) O[nt][i] = 0.0f;
    float m0r = -1e30f, m1r = -1e30f, l0 = 0.0f, l1 = 0.0f;

    float* Pw = Ps + warp * 16 * PS_LD;

    auto loadKV = [&](int j, int buf) {
        const float* Kt = Kg + (size_t)j * 64 * DD;
        const float* Vt = Vg + (size_t)j * 64 * DD;
        float* Kd = Ks + buf * 64 * KS_LD;
        float* Vd = Vs + buf * 64 * VS_LD;
        #pragma unroll
        for (int i = 0; i < 8; i++) {
            int idx = tid + i * 128; int r = idx >> 4, c = idx & 15;
            cpa16(Kd + r * KS_LD + c * 4, Kt + r * DD + c * 4);
        }
        #pragma unroll
        for (int i = 0; i < 8; i++) {
            int idx = tid + i * 128; int r = idx >> 4, c = idx & 15;
            cpa16(Vd + r * VS_LD + c * 4, Vt + r * DD + c * 4);
        }
        CP_COMMIT();
    };

    loadKV(0, 0);
    for (int j = 0; j < NN / 64; j++) {
        if (j + 1 < NN / 64) { loadKV(j + 1, (j + 1) & 1); CP_WAIT1(); }
        else                 { CP_WAIT0(); }
        __syncthreads();

        const float* Kb = Ks + (j & 1) * 64 * KS_LD;
        const float* Vb = Vs + (j & 1) * 64 * VS_LD;

        float S[8][4];
        #pragma unroll
        for (int nt = 0; nt < 8; nt++)
            #pragma unroll
            for (int i = 0; i < 4; i++) S[nt][i] = 0.0f;
        #pragma unroll
        for (int k = 0; k < 8; k++) {
            #pragma unroll
            for (int nt = 0; nt < 8; nt++) {
                const float* q = Kb + (nt * 8 + g) * KS_LD + k * 8 + t;
                uint32_t bf[2] = { fb(q[0]), fb(q[4]) };
                mma8(S[nt], qf[k], bf);
            }
        }

        float mx0 = -1e30f, mx1 = -1e30f;
        #pragma unroll
        for (int nt = 0; nt < 8; nt++) {
            mx0 = fmaxf(mx0, fmaxf(S[nt][0], S[nt][1]));
            mx1 = fmaxf(mx1, fmaxf(S[nt][2], S[nt][3]));
        }
        mx0 = fmaxf(mx0, __shfl_xor_sync(0xffffffffu, mx0, 1));
        mx0 = fmaxf(mx0, __shfl_xor_sync(0xffffffffu, mx0, 2));
        mx1 = fmaxf(mx1, __shfl_xor_sync(0xffffffffu, mx1, 1));
        mx1 = fmaxf(mx1, __shfl_xor_sync(0xffffffffu, mx1, 2));
        float mn0 = fmaxf(m0r, mx0), mn1 = fmaxf(m1r, mx1);
        float a0 = __expf(m0r - mn0), a1 = __expf(m1r - mn1);
        float s0 = 0.0f, s1 = 0.0f;
        #pragma unroll
        for (int nt = 0; nt < 8; nt++) {
            float p00 = __expf(S[nt][0] - mn0);
            float p01 = __expf(S[nt][1] - mn0);
            float p10 = __expf(S[nt][2] - mn1);
            float p11 = __expf(S[nt][3] - mn1);
            s0 += p00 + p01; s1 += p10 + p11;
            int c = nt * 8 + 2 * t;
            Pw[g * PS_LD + c]           = to_tf32(p00);
            Pw[g * PS_LD + c + 1]       = to_tf32(p01);
            Pw[(g + 8) * PS_LD + c]     = to_tf32(p10);
            Pw[(g + 8) * PS_LD + c + 1] = to_tf32(p11);
        }
        s0 += __shfl_xor_sync(0xffffffffu, s0, 1);
        s0 += __shfl_xor_sync(0xffffffffu, s0, 2);
        s1 += __shfl_xor_sync(0xffffffffu, s1, 1);
        s1 += __shfl_xor_sync(0xffffffffu, s1, 2);
        l0 = l0 * a0 + s0; l1 = l1 * a1 + s1;
        m0r = mn0; m1r = mn1;
        #pragma unroll
        for (int nt = 0; nt < 8; nt++) {
            O[nt][0] *= a0; O[nt][1] *= a0;
            O[nt][2] *= a1; O[nt][3] *= a1;
        }
        __syncwarp();

        #pragma unroll
        for (int k = 0; k < 8; k++) {
            uint32_t pa[4];
            const float* pp = Pw + g * PS_LD + k * 8 + t;
            pa[0] = fb(pp[0]);
            pa[1] = fb(pp[8 * PS_LD]);
            pa[2] = fb(pp[4]);
            pa[3] = fb(pp[8 * PS_LD + 4]);
            #pragma unroll
            for (int nt = 0; nt < 8; nt++) {
                const float* q = Vb + (k * 8 + t) * VS_LD + nt * 8 + g;
                uint32_t bf[2] = { fb(q[0]), fb(q[4 * VS_LD]) };
                mma8(O[nt], pa, bf);
            }
        }
        __syncthreads();
    }

    // write out [b, n, h*64+d] in A-PERMUTED layout (feeds O-proj GEMM):
    // logical col j within 8-group -> physical (j&3)*2 + (j>>2)
    {
        int b = bh >> 4, h = bh & 15;
        float i0 = 1.0f / l0, i1 = 1.0f / l1;
        int r = q0 + warp * 16 + g;
        float* d0 = Aout + ((size_t)(b * NN + r)) * EE + h * 64;
        float* d1 = d0 + (size_t)8 * EE;
        int j0 = 2 * t, j1 = 2 * t + 1;
        int p0 = (j0 & 3) * 2 + (j0 >> 2);
        int p1 = (j1 & 3) * 2 + (j1 >> 2);
        #pragma unroll
        for (int nt = 0; nt < 8; nt++) {
            int base = nt * 8;
            d0[base + p0] = to_tf32(O[nt][0] * i0);
            d0[base + p1] = to_tf32(O[nt][1] * i0);
            d1[base + p0] = to_tf32(O[nt][2] * i1);
            d1[base + p1] = to_tf32(O[nt][3] * i1);
        }
    }
}

// ---------------------------------------------------------------- launch
extern "C" void kernel_launch(void* const* d_in, const int* in_sizes, int n_in,
                              void* d_out, int out_size)
{
    const float* x  = (const float*)d_in[0];
    const float* Wq = (const float*)d_in[1];
    const float* bq = (const float*)d_in[2];
    const float* Wk = (const float*)d_in[3];
    const float* bk = (const float*)d_in[4];
    const float* Wv = (const float*)d_in[5];
    const float* bv = (const float*)d_in[6];
    const float* Wo = (const float*)d_in[7];
    const float* bo = (const float*)d_in[8];

    float *Xp, *Wcp, *Bcp, *QKVp, *Ap;
    cudaGetSymbolAddress((void**)&Xp,   g_X);
    cudaGetSymbolAddress((void**)&Wcp,  g_Wc);
    cudaGetSymbolAddress((void**)&Bcp,  g_Bc);
    cudaGetSymbolAddress((void**)&QKVp, g_QKV);
    cudaGetSymbolAddress((void**)&Ap,   g_A);

    cudaFuncSetAttribute(gemm_tf32, cudaFuncAttributeMaxDynamicSharedMemorySize, GEMM_SMEM);
    cudaFuncSetAttribute(attn_kernel, cudaFuncAttributeMaxDynamicSharedMemorySize, ATTN_SMEM);

    // conversions
    {
        int n4x = MM * EE / 4;          // 2,097,152
        int n4w = EE * EE / 4;          // 262,144
        conv_perm<<<(n4x + 255) / 256, 256>>>(x,  Xp, n4x);
        conv_tf32<<<(n4w + 255) / 256, 256>>>(Wq, Wcp + (size_t)0 * EE * EE, n4w);
        conv_tf32<<<(n4w + 255) / 256, 256>>>(Wk, Wcp + (size_t)1 * EE * EE, n4w);
        conv_tf32<<<(n4w + 255) / 256, 256>>>(Wv, Wcp + (size_t)2 * EE * EE, n4w);
        conv_tf32<<<(n4w + 255) / 256, 256>>>(Wo, Wcp + (size_t)3 * EE * EE, n4w);
        concat_bias<<<4, 256>>>(bq, bk, bv, Bcp);
    }

    // fused QKV: N=3072
    gemm_tf32<<<dim3(3 * EE / 128, MM / 128), 128, GEMM_SMEM>>>(Xp, Wcp, Bcp, QKVp, 1);

    attn_kernel<<<dim3(NN / 64, BB * HH), 128, ATTN_SMEM>>>(
        QKVp, QKVp + (size_t)MM * EE, QKVp + (size_t)2 * MM * EE, Ap);

    // O-projection
    gemm_tf32<<<dim3(EE / 128, MM / 128), 128, GEMM_SMEM>>>(
        Ap, Wcp + (size_t)3 * EE * EE, bo, (float*)d_out, 0);
}